// round 2
// baseline (speedup 1.0000x reference)
#include <cuda_runtime.h>
#include <math.h>

#define N      4096
#define NDIM   1024
#define NOUT   16
#define DIN    64
#define BK     64
#define NB     (NDIM/BK)   // 16
#define TS     128         // s-kernel tile

// ---------------- scratch (device globals) ----------------
__device__ float g_F[(size_t)N * NDIM];                 // F = tanh(x Wf), [n][i]
__device__ float g_A[(size_t)NOUT * NDIM * NDIM];       // working trailing matrix
__device__ float g_Lm[(size_t)NOUT * NDIM * NDIM];      // L off-diag panel tiles (dense, lower)
__device__ float g_Wm[(size_t)NOUT * NDIM * NDIM];      // W = L^{-1} (dense, upper zeroed)
__device__ float g_Linv[(size_t)NOUT * NB * BK * BK];   // diag-block inverses
__device__ float g_spart[(size_t)NOUT * (NDIM / TS) * N]; // s partials [k][i2][n]

// ---------------- F = tanh(x @ Wf) ----------------
__global__ __launch_bounds__(256) void k_F(const float* __restrict__ x,
                                           const float* __restrict__ Wf) {
    __shared__ float xs[16][DIN];
    int n0 = blockIdx.y * 16;
    int i  = blockIdx.x * 256 + threadIdx.x;
    for (int t = threadIdx.x; t < 16 * DIN; t += 256)
        xs[t / DIN][t % DIN] = x[(size_t)(n0 + t / DIN) * DIN + (t % DIN)];
    __syncthreads();
    float acc[16];
#pragma unroll
    for (int nn = 0; nn < 16; nn++) acc[nn] = 0.f;
    for (int d = 0; d < DIN; d++) {
        float wf = Wf[(size_t)d * NDIM + i];
#pragma unroll
        for (int nn = 0; nn < 16; nn++) acc[nn] += xs[nn][d] * wf;
    }
#pragma unroll
    for (int nn = 0; nn < 16; nn++)
        g_F[(size_t)(n0 + nn) * NDIM + i] = tanhf(acc[nn]);
}

// ---------------- m = F @ w^T ----------------
__global__ __launch_bounds__(256) void k_m(const float* __restrict__ w,
                                           float* __restrict__ out_m) {
    int warp = threadIdx.x >> 5, lane = threadIdx.x & 31;
    int n = blockIdx.x * 8 + warp;
    const float* Frow = &g_F[(size_t)n * NDIM];
    for (int k = 0; k < NOUT; k++) {
        float s = 0.f;
        for (int i = lane; i < NDIM; i += 32) s += Frow[i] * w[(size_t)k * NDIM + i];
#pragma unroll
        for (int o = 16; o > 0; o >>= 1) s += __shfl_down_sync(0xffffffffu, s, o);
        if (lane == 0) out_m[(size_t)n * NOUT + k] = s;
    }
}

// ---------------- copy P -> A (float4) and zero W ----------------
__global__ __launch_bounds__(256) void k_prep(const float* __restrict__ P) {
    size_t idx = ((size_t)blockIdx.x * 256 + threadIdx.x) * 4;
    *(float4*)&g_A[idx]  = *(const float4*)&P[idx];
    float4 z = {0.f, 0.f, 0.f, 0.f};
    *(float4*)&g_Wm[idx] = z;
}

// ---------------- fused Cholesky step: diag chol (redundant) + panel TRSM + SYRK ----------------
// grid (NOUT, npairs); each CTA handles trailing tile pair (rt, ct)
__global__ __launch_bounds__(256) void k_cholstep(int jb) {
    __shared__ float B1[64][65];
    __shared__ float B2[64][65];
    int k  = blockIdx.x;
    int p  = blockIdx.y;
    int nt = NB - 1 - jb;
    int rt = 0;
    if (nt > 0) { while ((rt + 1) * (rt + 2) / 2 <= p) rt++; }
    int ct = (nt > 0) ? p - rt * (rt + 1) / 2 : 0;
    int j0 = jb * BK;
    float* A = g_A + (size_t)k * NDIM * NDIM;

    // load diag block
    for (int t = threadIdx.x; t < 64 * 64; t += 256)
        B1[t / 64][t % 64] = A[(size_t)(j0 + t / 64) * NDIM + j0 + (t % 64)];
    __syncthreads();
    // unblocked Cholesky (lower) on B1
    for (int j = 0; j < 64; j++) {
        if (threadIdx.x == 0) B1[j][j] = sqrtf(B1[j][j]);
        __syncthreads();
        float dj = B1[j][j];
        for (int r = j + 1 + threadIdx.x; r < 64; r += 256) B1[r][j] /= dj;
        __syncthreads();
        int m = 63 - j;
        for (int t = threadIdx.x; t < m * m; t += 256) {
            int r = j + 1 + t / m, c = j + 1 + t % m;
            B1[r][c] -= B1[r][j] * B1[c][j];
        }
        __syncthreads();
    }
    // invert lower triangle into B2 (incl. upper zeros)
    if (threadIdx.x < 64) {
        int c = threadIdx.x;
        for (int r = 0; r < c; r++) B2[r][c] = 0.f;
        B2[c][c] = 1.f / B1[c][c];
        for (int r = c + 1; r < 64; r++) {
            float ssum = 0.f;
            for (int t = c; t < r; t++) ssum += B1[r][t] * B2[t][c];
            B2[r][c] = -ssum / B1[r][r];
        }
    }
    __syncthreads();
    if (p == 0) {
        float* Lout = &g_Linv[((size_t)k * NB + jb) * BK * BK];
        for (int t = threadIdx.x; t < 64 * 64; t += 256)
            Lout[t] = B2[t / 64][t % 64];
    }
    if (nt == 0) return;

    int r0 = j0 + 64 + rt * 64, c0 = j0 + 64 + ct * 64;
    int tr = (threadIdx.x / 16) * 4, tc = (threadIdx.x % 16) * 4;

    // TRSM row-tile rt: Lr = PanR @ Li^T  (B1 <- raw panel, B2 = Li)
    __syncthreads();
    for (int t = threadIdx.x; t < 64 * 64; t += 256)
        B1[t / 64][t % 64] = A[(size_t)(r0 + t / 64) * NDIM + j0 + (t % 64)];
    __syncthreads();
    float accR[4][4] = {};
    for (int t = 0; t < 64; t++) {
        float a[4], b[4];
#pragma unroll
        for (int u = 0; u < 4; u++) { a[u] = B1[tr + u][t]; b[u] = B2[tc + u][t]; }
#pragma unroll
        for (int u = 0; u < 4; u++)
#pragma unroll
            for (int v = 0; v < 4; v++) accR[u][v] += a[u] * b[v];
    }
    float accC[4][4];
    if (ct != rt) {
        __syncthreads();
        for (int t = threadIdx.x; t < 64 * 64; t += 256)
            B1[t / 64][t % 64] = A[(size_t)(c0 + t / 64) * NDIM + j0 + (t % 64)];
        __syncthreads();
#pragma unroll
        for (int u = 0; u < 4; u++)
#pragma unroll
            for (int v = 0; v < 4; v++) accC[u][v] = 0.f;
        for (int t = 0; t < 64; t++) {
            float a[4], b[4];
#pragma unroll
            for (int u = 0; u < 4; u++) { a[u] = B1[tr + u][t]; b[u] = B2[tc + u][t]; }
#pragma unroll
            for (int u = 0; u < 4; u++)
#pragma unroll
                for (int v = 0; v < 4; v++) accC[u][v] += a[u] * b[v];
        }
    } else {
#pragma unroll
        for (int u = 0; u < 4; u++)
#pragma unroll
            for (int v = 0; v < 4; v++) accC[u][v] = accR[u][v];
    }
    // materialize Lr -> B1, Lc -> B2
    __syncthreads();
#pragma unroll
    for (int u = 0; u < 4; u++)
#pragma unroll
        for (int v = 0; v < 4; v++) {
            B1[tr + u][tc + v] = accR[u][v];
            B2[tr + u][tc + v] = accC[u][v];
        }
    // unique writer of the finished L panel tile
    if (rt == ct) {
        float* Lm = g_Lm + (size_t)k * NDIM * NDIM;
#pragma unroll
        for (int u = 0; u < 4; u++)
#pragma unroll
            for (int v = 0; v < 4; v++)
                Lm[(size_t)(r0 + tr + u) * NDIM + j0 + tc + v] = accR[u][v];
    }
    __syncthreads();
    // SYRK: A[r0,c0] -= Lr @ Lc^T
    float acc3[4][4] = {};
    for (int t = 0; t < 64; t++) {
        float a[4], b[4];
#pragma unroll
        for (int u = 0; u < 4; u++) { a[u] = B1[tr + u][t]; b[u] = B2[tc + u][t]; }
#pragma unroll
        for (int u = 0; u < 4; u++)
#pragma unroll
            for (int v = 0; v < 4; v++) acc3[u][v] += a[u] * b[v];
    }
#pragma unroll
    for (int u = 0; u < 4; u++)
#pragma unroll
        for (int v = 0; v < 4; v++) {
            size_t idx = (size_t)(r0 + tr + u) * NDIM + c0 + tc + v;
            A[idx] -= acc3[u][v];
        }
}

// ---------------- W diag blocks: W_jj = Linv_jj ----------------
__global__ __launch_bounds__(256) void k_wdiag() {
    int k = blockIdx.x, j = blockIdx.y;
    const float* Li = &g_Linv[((size_t)k * NB + j) * BK * BK];
    float* W = g_Wm + (size_t)k * NDIM * NDIM;
    for (int t = threadIdx.x; t < 64 * 64; t += 256)
        W[(size_t)(j * 64 + t / 64) * NDIM + j * 64 + (t % 64)] = Li[t];
}

// ---------------- W off-diag level d: W_ij = -Linv_ii * sum_t L_it W_tj ----------------
__global__ __launch_bounds__(256) void k_winv(int d) {
    __shared__ float Ta[64][65];
    __shared__ float Tb[64][65];
    int k = blockIdx.x, j = blockIdx.y, i = j + d;
    const float* Lm = g_Lm + (size_t)k * NDIM * NDIM;
    float* W = g_Wm + (size_t)k * NDIM * NDIM;
    const float* Li = &g_Linv[((size_t)k * NB + i) * BK * BK];
    int tr = (threadIdx.x / 16) * 4, tc = (threadIdx.x % 16) * 4;
    float acc[4][4] = {};
    for (int t = j; t < i; t++) {
        __syncthreads();
        for (int q = threadIdx.x; q < 64 * 64; q += 256) {
            Ta[q / 64][q % 64] = Lm[(size_t)(i * 64 + q / 64) * NDIM + t * 64 + (q % 64)];
            Tb[q / 64][q % 64] = W[(size_t)(t * 64 + q / 64) * NDIM + j * 64 + (q % 64)];
        }
        __syncthreads();
        for (int kk = 0; kk < 64; kk++) {
            float a[4], b[4];
#pragma unroll
            for (int u = 0; u < 4; u++) { a[u] = Ta[tr + u][kk]; b[u] = Tb[kk][tc + u]; }
#pragma unroll
            for (int u = 0; u < 4; u++)
#pragma unroll
                for (int v = 0; v < 4; v++) acc[u][v] += a[u] * b[v];
        }
    }
    __syncthreads();
#pragma unroll
    for (int u = 0; u < 4; u++)
#pragma unroll
        for (int v = 0; v < 4; v++) Ta[tr + u][tc + v] = acc[u][v];
    for (int q = threadIdx.x; q < 64 * 64; q += 256)
        Tb[q / 64][q % 64] = Li[q];
    __syncthreads();
    float z[4][4] = {};
    for (int kk = 0; kk < 64; kk++) {
        float a[4], b[4];
#pragma unroll
        for (int u = 0; u < 4; u++) { a[u] = Tb[tr + u][kk]; b[u] = Ta[kk][tc + u]; }
#pragma unroll
        for (int u = 0; u < 4; u++)
#pragma unroll
            for (int v = 0; v < 4; v++) z[u][v] += a[u] * b[v];
    }
#pragma unroll
    for (int u = 0; u < 4; u++)
#pragma unroll
        for (int v = 0; v < 4; v++)
            W[(size_t)(i * 64 + tr + u) * NDIM + j * 64 + tc + v] = -z[u][v];
}

// ---------------- s: per (k, i2, n0) compute Z block = W[i2-rows] @ F^T, square-reduce ----------------
// grid (N/TS, NDIM/TS, NOUT), block 256, 8x8 micro
__global__ __launch_bounds__(256, 2) void k_s() {
    __shared__ float As[8][TS];   // W chunk transposed: As[kc][m]
    __shared__ float Bs[8][TS];   // F chunk transposed: Bs[kc][n]
    __shared__ float red[16][TS];
    int n0 = blockIdx.x * TS;
    int i2 = blockIdx.y;
    int m0 = i2 * TS;
    int k  = blockIdx.z;
    const float* Wk = g_Wm + (size_t)k * NDIM * NDIM;
    int tx = threadIdx.x % 16, ty = threadIdx.x / 16;
    int lrow = threadIdx.x >> 1, lc4 = (threadIdx.x & 1) * 4;
    float acc[8][8];
#pragma unroll
    for (int u = 0; u < 8; u++)
#pragma unroll
        for (int v = 0; v < 8; v++) acc[u][v] = 0.f;
    int Kend = m0 + TS;  // W rows m0..m0+127 have zero cols beyond (zero-filled upper)
    for (int t = 0; t < Kend; t += 8) {
        float4 wv = *(const float4*)&Wk[(size_t)(m0 + lrow) * NDIM + t + lc4];
        float4 fv = *(const float4*)&g_F[(size_t)(n0 + lrow) * NDIM + t + lc4];
        __syncthreads();
        As[lc4 + 0][lrow] = wv.x; As[lc4 + 1][lrow] = wv.y;
        As[lc4 + 2][lrow] = wv.z; As[lc4 + 3][lrow] = wv.w;
        Bs[lc4 + 0][lrow] = fv.x; Bs[lc4 + 1][lrow] = fv.y;
        Bs[lc4 + 2][lrow] = fv.z; Bs[lc4 + 3][lrow] = fv.w;
        __syncthreads();
#pragma unroll
        for (int kc = 0; kc < 8; kc++) {
            float a[8], b[8];
            *(float4*)&a[0] = *(const float4*)&As[kc][ty * 8];
            *(float4*)&a[4] = *(const float4*)&As[kc][ty * 8 + 4];
            *(float4*)&b[0] = *(const float4*)&Bs[kc][tx * 8];
            *(float4*)&b[4] = *(const float4*)&Bs[kc][tx * 8 + 4];
#pragma unroll
            for (int u = 0; u < 8; u++)
#pragma unroll
                for (int v = 0; v < 8; v++) acc[u][v] += a[u] * b[v];
        }
    }
    // square-reduce over m within thread, then across ty groups
#pragma unroll
    for (int v = 0; v < 8; v++) {
        float pv = 0.f;
#pragma unroll
        for (int u = 0; u < 8; u++) pv += acc[u][v] * acc[u][v];
        red[ty][tx * 8 + v] = pv;
    }
    __syncthreads();
    if (threadIdx.x < TS) {
        float tot = 0.f;
#pragma unroll
        for (int g = 0; g < 16; g++) tot += red[g][threadIdx.x];
        g_spart[((size_t)k * (NDIM / TS) + i2) * N + n0 + threadIdx.x] = tot;
    }
}

// ---------------- reduce s partials -> out_s ----------------
__global__ __launch_bounds__(256) void k_sred(float* __restrict__ out_s) {
    int idx = blockIdx.x * 256 + threadIdx.x;   // over N*NOUT
    int n = idx / NOUT, k = idx % NOUT;
    float tot = 0.f;
#pragma unroll
    for (int i2 = 0; i2 < NDIM / TS; i2++)
        tot += g_spart[((size_t)k * (NDIM / TS) + i2) * N + n];
    out_s[idx] = tot;
}

// ---------------- launch ----------------
extern "C" void kernel_launch(void* const* d_in, const int* in_sizes, int n_in,
                              void* d_out, int out_size) {
    const float* x  = (const float*)d_in[0];
    const float* Wf = (const float*)d_in[1];
    const float* w  = (const float*)d_in[2];
    const float* P  = (const float*)d_in[3];
    float* out   = (float*)d_out;
    float* out_m = out;
    float* out_s = out + (size_t)N * NOUT;

    k_F<<<dim3(NDIM / 256, N / 16), 256>>>(x, Wf);
    k_m<<<N / 8, 256>>>(w, out_m);
    k_prep<<<(unsigned)((size_t)NOUT * NDIM * NDIM / (256 * 4)), 256>>>(P);

    for (int jb = 0; jb < NB; jb++) {
        int nt = NB - 1 - jb;
        int npairs = nt > 0 ? nt * (nt + 1) / 2 : 1;
        k_cholstep<<<dim3(NOUT, npairs), 256>>>(jb);
    }
    k_wdiag<<<dim3(NOUT, NB), 256>>>();
    for (int d = 1; d < NB; d++)
        k_winv<<<dim3(NOUT, NB - d), 256>>>(d);

    k_s<<<dim3(N / TS, NDIM / TS, NOUT), 256>>>();
    k_sred<<<(N * NOUT) / 256, 256>>>(out_s);
}

// round 4
// speedup vs baseline: 1.1473x; 1.1473x over previous
#include <cuda_runtime.h>
#include <math.h>

#define N      4096
#define NDIM   1024
#define NOUT   16
#define DIN    64
#define BK     64
#define NB     (NDIM/BK)   // 16
#define TS     128         // s-kernel tile

// ---------------- scratch (device globals) ----------------
__device__ float g_F[(size_t)N * NDIM];                 // F = tanh(x Wf), [n][i]
__device__ float g_A[(size_t)NOUT * NDIM * NDIM];       // working trailing matrix
__device__ float g_Lm[(size_t)NOUT * NDIM * NDIM];      // L off-diag panel tiles
__device__ float g_Wm[(size_t)NOUT * NDIM * NDIM];      // W = L^{-1} (dense, upper zeroed)
__device__ float g_Linv[(size_t)NOUT * NB * BK * BK];   // diag-block inverses
__device__ float g_spart[(size_t)NOUT * (NDIM / TS) * N]; // s partials [k][i2][n]

// ---------------- F = tanh(x @ Wf) ----------------
__global__ __launch_bounds__(256) void k_F(const float* __restrict__ x,
                                           const float* __restrict__ Wf) {
    __shared__ float xs[16][DIN];
    int n0 = blockIdx.y * 16;
    int i  = blockIdx.x * 256 + threadIdx.x;
    for (int t = threadIdx.x; t < 16 * DIN; t += 256)
        xs[t >> 6][t & 63] = x[(size_t)(n0 + (t >> 6)) * DIN + (t & 63)];
    __syncthreads();
    float acc[16];
#pragma unroll
    for (int nn = 0; nn < 16; nn++) acc[nn] = 0.f;
    for (int d = 0; d < DIN; d++) {
        float wf = Wf[(size_t)d * NDIM + i];
#pragma unroll
        for (int nn = 0; nn < 16; nn++) acc[nn] += xs[nn][d] * wf;
    }
#pragma unroll
    for (int nn = 0; nn < 16; nn++)
        g_F[(size_t)(n0 + nn) * NDIM + i] = tanhf(acc[nn]);
}

// ---------------- m = F @ w^T ----------------
__global__ __launch_bounds__(256) void k_m(const float* __restrict__ w,
                                           float* __restrict__ out_m) {
    int warp = threadIdx.x >> 5, lane = threadIdx.x & 31;
    int n = blockIdx.x * 8 + warp;
    const float* Frow = &g_F[(size_t)n * NDIM];
    for (int k = 0; k < NOUT; k++) {
        float s = 0.f;
        for (int i = lane; i < NDIM; i += 32) s += Frow[i] * w[(size_t)k * NDIM + i];
#pragma unroll
        for (int o = 16; o > 0; o >>= 1) s += __shfl_down_sync(0xffffffffu, s, o);
        if (lane == 0) out_m[(size_t)n * NOUT + k] = s;
    }
}

// ---------------- copy P -> A (float4) and zero W ----------------
__global__ __launch_bounds__(256) void k_prep(const float* __restrict__ P) {
    size_t idx = ((size_t)blockIdx.x * 256 + threadIdx.x) * 4;
    *(float4*)&g_A[idx]  = *(const float4*)&P[idx];
    float4 z = {0.f, 0.f, 0.f, 0.f};
    *(float4*)&g_Wm[idx] = z;
}

// ---------------- diag block: Cholesky + triangular inverse (grid NOUT, 64 thr) ----------------
__global__ __launch_bounds__(64) void k_diag(int jb) {
    __shared__ float D[64][65];
    __shared__ float X[64][65];
    __shared__ float invd[64];
    int k  = blockIdx.x;
    int j0 = jb * BK;
    int tid = threadIdx.x;
    float* A = g_A + (size_t)k * NDIM * NDIM;
    for (int t = tid; t < 64 * 64; t += 64)
        D[t >> 6][t & 63] = A[(size_t)(j0 + (t >> 6)) * NDIM + j0 + (t & 63)];
    __syncthreads();
    // right-looking Cholesky, row-per-thread
    for (int j = 0; j < 64; j++) {
        if (tid == 0) {
            float d = D[j][j];
            float r = rsqrtf(d);
            invd[j] = r;
            D[j][j] = d * r;    // sqrt(d)
        }
        __syncthreads();
        float s = invd[j];
        if (tid > j) D[tid][j] *= s;
        __syncthreads();
        if (tid > j) {
            float lrj = D[tid][j];
            for (int c = j + 1; c <= tid; c++) D[tid][c] -= lrj * D[c][j];
        }
    }
    __syncthreads();
    // invert: X = L^{-1}, column per thread, upper zeroed
    {
        int c = tid;
        for (int r = 0; r < c; r++) X[r][c] = 0.f;
        X[c][c] = invd[c];
        for (int r = c + 1; r < 64; r++) {
            float s = 0.f;
            for (int t = c; t < r; t++) s += D[r][t] * X[t][c];
            X[r][c] = -s * invd[r];
        }
    }
    __syncthreads();
    float* Lout = &g_Linv[((size_t)k * NB + jb) * BK * BK];
    for (int t = tid; t < 64 * 64 / 4; t += 64) {
        float4 v = make_float4(X[(t * 4) >> 6][(t * 4) & 63],
                               X[(t * 4 + 1) >> 6][(t * 4 + 1) & 63],
                               X[(t * 4 + 2) >> 6][(t * 4 + 2) & 63],
                               X[(t * 4 + 3) >> 6][(t * 4 + 3) & 63]);
        *(float4*)&Lout[t * 4] = v;
    }
}

// ---------------- fused panel TRSM (redundant, from Linv) + SYRK ----------------
// grid (NOUT, nt*(nt+1)/2)
__global__ __launch_bounds__(256) void k_step(int jb) {
    __shared__ float B1[64][65];
    __shared__ float B2[64][65];
    int k  = blockIdx.x;
    int p  = blockIdx.y;
    int rt = 0;
    while ((rt + 1) * (rt + 2) / 2 <= p) rt++;
    int ct = p - rt * (rt + 1) / 2;
    int j0 = jb * BK;
    int r0 = j0 + 64 + rt * 64, c0 = j0 + 64 + ct * 64;
    float* A = g_A + (size_t)k * NDIM * NDIM;
    const float* Li = &g_Linv[((size_t)k * NB + jb) * BK * BK];
    int tr = (threadIdx.x >> 4) * 4, tc = (threadIdx.x & 15) * 4;

    // B2 <- Linv, B1 <- raw row panel
    for (int t = threadIdx.x; t < 64 * 64; t += 256) {
        B2[t >> 6][t & 63] = Li[t];
        B1[t >> 6][t & 63] = A[(size_t)(r0 + (t >> 6)) * NDIM + j0 + (t & 63)];
    }
    __syncthreads();
    float accR[4][4] = {};
    for (int t = 0; t < 64; t++) {
        float a[4], b[4];
#pragma unroll
        for (int u = 0; u < 4; u++) { a[u] = B1[tr + u][t]; b[u] = B2[tc + u][t]; }
#pragma unroll
        for (int u = 0; u < 4; u++)
#pragma unroll
            for (int v = 0; v < 4; v++) accR[u][v] += a[u] * b[v];
    }
    float accC[4][4];
    if (ct != rt) {
        __syncthreads();
        for (int t = threadIdx.x; t < 64 * 64; t += 256)
            B1[t >> 6][t & 63] = A[(size_t)(c0 + (t >> 6)) * NDIM + j0 + (t & 63)];
        __syncthreads();
#pragma unroll
        for (int u = 0; u < 4; u++)
#pragma unroll
            for (int v = 0; v < 4; v++) accC[u][v] = 0.f;
        for (int t = 0; t < 64; t++) {
            float a[4], b[4];
#pragma unroll
            for (int u = 0; u < 4; u++) { a[u] = B1[tr + u][t]; b[u] = B2[tc + u][t]; }
#pragma unroll
            for (int u = 0; u < 4; u++)
#pragma unroll
                for (int v = 0; v < 4; v++) accC[u][v] += a[u] * b[v];
        }
    } else {
#pragma unroll
        for (int u = 0; u < 4; u++)
#pragma unroll
            for (int v = 0; v < 4; v++) accC[u][v] = accR[u][v];
    }
    __syncthreads();
#pragma unroll
    for (int u = 0; u < 4; u++)
#pragma unroll
        for (int v = 0; v < 4; v++) {
            B1[tr + u][tc + v] = accR[u][v];
            B2[tr + u][tc + v] = accC[u][v];
        }
    if (rt == ct) {
        float* Lm = g_Lm + (size_t)k * NDIM * NDIM;
#pragma unroll
        for (int u = 0; u < 4; u++)
#pragma unroll
            for (int v = 0; v < 4; v++)
                Lm[(size_t)(r0 + tr + u) * NDIM + j0 + tc + v] = accR[u][v];
    }
    __syncthreads();
    float acc3[4][4] = {};
    for (int t = 0; t < 64; t++) {
        float a[4], b[4];
#pragma unroll
        for (int u = 0; u < 4; u++) { a[u] = B1[tr + u][t]; b[u] = B2[tc + u][t]; }
#pragma unroll
        for (int u = 0; u < 4; u++)
#pragma unroll
            for (int v = 0; v < 4; v++) acc3[u][v] += a[u] * b[v];
    }
#pragma unroll
    for (int u = 0; u < 4; u++)
#pragma unroll
        for (int v = 0; v < 4; v++) {
            size_t idx = (size_t)(r0 + tr + u) * NDIM + c0 + tc + v;
            A[idx] -= acc3[u][v];
        }
}

// ---------------- W diag blocks ----------------
__global__ __launch_bounds__(256) void k_wdiag() {
    int k = blockIdx.x, j = blockIdx.y;
    const float* Li = &g_Linv[((size_t)k * NB + j) * BK * BK];
    float* W = g_Wm + (size_t)k * NDIM * NDIM;
    for (int t = threadIdx.x; t < 64 * 64; t += 256)
        W[(size_t)(j * 64 + (t >> 6)) * NDIM + j * 64 + (t & 63)] = Li[t];
}

// ---------------- W off-diag level d ----------------
__global__ __launch_bounds__(256) void k_winv(int d) {
    __shared__ float Ta[64][65];
    __shared__ float Tb[64][65];
    int k = blockIdx.x, j = blockIdx.y, i = j + d;
    const float* Lm = g_Lm + (size_t)k * NDIM * NDIM;
    float* W = g_Wm + (size_t)k * NDIM * NDIM;
    const float* Li = &g_Linv[((size_t)k * NB + i) * BK * BK];
    int tr = (threadIdx.x >> 4) * 4, tc = (threadIdx.x & 15) * 4;
    float acc[4][4] = {};
    for (int t = j; t < i; t++) {
        __syncthreads();
        for (int q = threadIdx.x; q < 64 * 64; q += 256) {
            Ta[q >> 6][q & 63] = Lm[(size_t)(i * 64 + (q >> 6)) * NDIM + t * 64 + (q & 63)];
            Tb[q >> 6][q & 63] = W[(size_t)(t * 64 + (q >> 6)) * NDIM + j * 64 + (q & 63)];
        }
        __syncthreads();
        for (int kk = 0; kk < 64; kk++) {
            float a[4], b[4];
#pragma unroll
            for (int u = 0; u < 4; u++) { a[u] = Ta[tr + u][kk]; b[u] = Tb[kk][tc + u]; }
#pragma unroll
            for (int u = 0; u < 4; u++)
#pragma unroll
                for (int v = 0; v < 4; v++) acc[u][v] += a[u] * b[v];
        }
    }
    __syncthreads();
#pragma unroll
    for (int u = 0; u < 4; u++)
#pragma unroll
        for (int v = 0; v < 4; v++) Ta[tr + u][tc + v] = acc[u][v];
    for (int q = threadIdx.x; q < 64 * 64; q += 256)
        Tb[q >> 6][q & 63] = Li[q];
    __syncthreads();
    float z[4][4] = {};
    for (int kk = 0; kk < 64; kk++) {
        float a[4], b[4];
#pragma unroll
        for (int u = 0; u < 4; u++) { a[u] = Tb[tr + u][kk]; b[u] = Ta[kk][tc + u]; }
#pragma unroll
        for (int u = 0; u < 4; u++)
#pragma unroll
            for (int v = 0; v < 4; v++) z[u][v] += a[u] * b[v];
    }
#pragma unroll
    for (int u = 0; u < 4; u++)
#pragma unroll
        for (int v = 0; v < 4; v++)
            W[(size_t)(i * 64 + tr + u) * NDIM + j * 64 + tc + v] = -z[u][v];
}

// ---------------- s: Z block = W-rows @ F^T, square-reduce (Z never hits DRAM) ----------------
// grid (N/TS, NDIM/TS, NOUT), block 256, 8x8 micro
__global__ __launch_bounds__(256, 2) void k_s() {
    __shared__ float As[8][TS];
    __shared__ float Bs[8][TS];
    __shared__ float red[16][TS];
    int n0 = blockIdx.x * TS;
    int i2 = blockIdx.y;
    int m0 = i2 * TS;
    int k  = blockIdx.z;
    const float* Wk = g_Wm + (size_t)k * NDIM * NDIM;
    int tx = threadIdx.x & 15, ty = threadIdx.x >> 4;
    int lrow = threadIdx.x >> 1, lc4 = (threadIdx.x & 1) * 4;
    float acc[8][8];
#pragma unroll
    for (int u = 0; u < 8; u++)
#pragma unroll
        for (int v = 0; v < 8; v++) acc[u][v] = 0.f;
    int Kend = m0 + TS;  // W is lower-triangular (upper zeroed)
    for (int t = 0; t < Kend; t += 8) {
        float4 wv = *(const float4*)&Wk[(size_t)(m0 + lrow) * NDIM + t + lc4];
        float4 fv = *(const float4*)&g_F[(size_t)(n0 + lrow) * NDIM + t + lc4];
        __syncthreads();
        As[lc4 + 0][lrow] = wv.x; As[lc4 + 1][lrow] = wv.y;
        As[lc4 + 2][lrow] = wv.z; As[lc4 + 3][lrow] = wv.w;
        Bs[lc4 + 0][lrow] = fv.x; Bs[lc4 + 1][lrow] = fv.y;
        Bs[lc4 + 2][lrow] = fv.z; Bs[lc4 + 3][lrow] = fv.w;
        __syncthreads();
#pragma unroll
        for (int kc = 0; kc < 8; kc++) {
            float a[8], b[8];
            *(float4*)&a[0] = *(const float4*)&As[kc][ty * 8];
            *(float4*)&a[4] = *(const float4*)&As[kc][ty * 8 + 4];
            *(float4*)&b[0] = *(const float4*)&Bs[kc][tx * 8];
            *(float4*)&b[4] = *(const float4*)&Bs[kc][tx * 8 + 4];
#pragma unroll
            for (int u = 0; u < 8; u++)
#pragma unroll
                for (int v = 0; v < 8; v++) acc[u][v] += a[u] * b[v];
        }
    }
#pragma unroll
    for (int v = 0; v < 8; v++) {
        float pv = 0.f;
#pragma unroll
        for (int u = 0; u < 8; u++) pv += acc[u][v] * acc[u][v];
        red[ty][tx * 8 + v] = pv;
    }
    __syncthreads();
    if (threadIdx.x < TS) {
        float tot = 0.f;
#pragma unroll
        for (int g = 0; g < 16; g++) tot += red[g][threadIdx.x];
        g_spart[((size_t)k * (NDIM / TS) + i2) * N + n0 + threadIdx.x] = tot;
    }
}

// ---------------- reduce s partials ----------------
__global__ __launch_bounds__(256) void k_sred(float* __restrict__ out_s) {
    int idx = blockIdx.x * 256 + threadIdx.x;
    int n = idx >> 4, k = idx & 15;
    float tot = 0.f;
#pragma unroll
    for (int i2 = 0; i2 < NDIM / TS; i2++)
        tot += g_spart[((size_t)k * (NDIM / TS) + i2) * N + n];
    out_s[idx] = tot;
}

// ---------------- launch ----------------
extern "C" void kernel_launch(void* const* d_in, const int* in_sizes, int n_in,
                              void* d_out, int out_size) {
    const float* x  = (const float*)d_in[0];
    const float* Wf = (const float*)d_in[1];
    const float* w  = (const float*)d_in[2];
    const float* P  = (const float*)d_in[3];
    float* out   = (float*)d_out;
    float* out_m = out;
    float* out_s = out + (size_t)N * NOUT;

    k_F<<<dim3(NDIM / 256, N / 16), 256>>>(x, Wf);
    k_m<<<N / 8, 256>>>(w, out_m);
    k_prep<<<(unsigned)((size_t)NOUT * NDIM * NDIM / (256 * 4)), 256>>>(P);

    for (int jb = 0; jb < NB; jb++) {
        k_diag<<<NOUT, 64>>>(jb);
        int nt = NB - 1 - jb;
        if (nt > 0)
            k_step<<<dim3(NOUT, nt * (nt + 1) / 2), 256>>>(jb);
    }
    k_wdiag<<<dim3(NOUT, NB), 256>>>();
    for (int d = 1; d < NB; d++)
        k_winv<<<dim3(NOUT, NB - d), 256>>>(d);

    k_s<<<dim3(N / TS, NDIM / TS, NOUT), 256>>>();
    k_sred<<<(N * NOUT) / 256, 256>>>(out_s);
}

// round 6
// speedup vs baseline: 1.2865x; 1.1213x over previous
#include <cuda_runtime.h>
#include <math.h>

#define N      4096
#define NDIM   1024
#define NOUT   16
#define DIN    64
#define BK     64
#define NB     (NDIM/BK)   // 16
#define TS     128         // s-kernel tile

// ---------------- scratch (device globals) ----------------
__device__ float g_F[(size_t)N * NDIM];                 // F = tanh(x Wf), [n][i]
__device__ float g_A[(size_t)NOUT * NDIM * NDIM];       // working trailing matrix
__device__ float g_Lm[(size_t)NOUT * NDIM * NDIM];      // L off-diag panel tiles
__device__ float g_Wm[(size_t)NOUT * NDIM * NDIM];      // W = L^{-1} (dense, upper zeroed)
__device__ float g_Linv[(size_t)NOUT * NB * BK * BK];   // diag-block inverses
__device__ float g_spart[(size_t)NOUT * (NDIM / TS) * N]; // s partials [k][i2][n]

__device__ __forceinline__ unsigned f2tf32(float x) {
    unsigned r;
    asm("cvt.rna.tf32.f32 %0, %1;" : "=r"(r) : "f"(x));
    return r;
}

// ---------------- F = tanh(x @ Wf) ----------------
__global__ __launch_bounds__(256) void k_F(const float* __restrict__ x,
                                           const float* __restrict__ Wf) {
    __shared__ float xs[16][DIN];
    int n0 = blockIdx.y * 16;
    int i  = blockIdx.x * 256 + threadIdx.x;
    for (int t = threadIdx.x; t < 16 * DIN; t += 256)
        xs[t >> 6][t & 63] = x[(size_t)(n0 + (t >> 6)) * DIN + (t & 63)];
    __syncthreads();
    float acc[16];
#pragma unroll
    for (int nn = 0; nn < 16; nn++) acc[nn] = 0.f;
    for (int d = 0; d < DIN; d++) {
        float wf = Wf[(size_t)d * NDIM + i];
#pragma unroll
        for (int nn = 0; nn < 16; nn++) acc[nn] += xs[nn][d] * wf;
    }
#pragma unroll
    for (int nn = 0; nn < 16; nn++)
        g_F[(size_t)(n0 + nn) * NDIM + i] = tanhf(acc[nn]);
}

// ---------------- m = F @ w^T ----------------
__global__ __launch_bounds__(256) void k_m(const float* __restrict__ w,
                                           float* __restrict__ out_m) {
    int warp = threadIdx.x >> 5, lane = threadIdx.x & 31;
    int n = blockIdx.x * 8 + warp;
    const float* Frow = &g_F[(size_t)n * NDIM];
    for (int k = 0; k < NOUT; k++) {
        float s = 0.f;
        for (int i = lane; i < NDIM; i += 32) s += Frow[i] * w[(size_t)k * NDIM + i];
#pragma unroll
        for (int o = 16; o > 0; o >>= 1) s += __shfl_down_sync(0xffffffffu, s, o);
        if (lane == 0) out_m[(size_t)n * NOUT + k] = s;
    }
}

// ---------------- copy P -> A (float4) and zero W ----------------
__global__ __launch_bounds__(256) void k_prep(const float* __restrict__ P) {
    size_t idx = ((size_t)blockIdx.x * 256 + threadIdx.x) * 4;
    *(float4*)&g_A[idx]  = *(const float4*)&P[idx];
    float4 z = {0.f, 0.f, 0.f, 0.f};
    *(float4*)&g_Wm[idx] = z;
}

// ---------------- diag block: Cholesky + triangular inverse (grid NOUT, 64 thr) ----------------
__global__ __launch_bounds__(64) void k_diag(int jb) {
    __shared__ float D[64][65];
    __shared__ float X[64][65];
    __shared__ float invd[64];
    int k  = blockIdx.x;
    int j0 = jb * BK;
    int tid = threadIdx.x;
    float* A = g_A + (size_t)k * NDIM * NDIM;
    for (int t = tid; t < 64 * 64; t += 64)
        D[t >> 6][t & 63] = A[(size_t)(j0 + (t >> 6)) * NDIM + j0 + (t & 63)];
    __syncthreads();
    for (int j = 0; j < 64; j++) {
        if (tid == 0) {
            float d = D[j][j];
            float r = rsqrtf(d);
            invd[j] = r;
            D[j][j] = d * r;
        }
        __syncthreads();
        float s = invd[j];
        if (tid > j) D[tid][j] *= s;
        __syncthreads();
        if (tid > j) {
            float lrj = D[tid][j];
            for (int c = j + 1; c <= tid; c++) D[tid][c] -= lrj * D[c][j];
        }
    }
    __syncthreads();
    {
        int c = tid;
        for (int r = 0; r < c; r++) X[r][c] = 0.f;
        X[c][c] = invd[c];
        for (int r = c + 1; r < 64; r++) {
            float s = 0.f;
            for (int t = c; t < r; t++) s += D[r][t] * X[t][c];
            X[r][c] = -s * invd[r];
        }
    }
    __syncthreads();
    float* Lout = &g_Linv[((size_t)k * NB + jb) * BK * BK];
    for (int t = tid; t < 64 * 64; t += 64)
        Lout[t] = X[t >> 6][t & 63];
}

// ---------------- fused panel TRSM (from Linv) + SYRK ----------------
__global__ __launch_bounds__(256) void k_step(int jb) {
    __shared__ float B1[64][65];
    __shared__ float B2[64][65];
    int k  = blockIdx.x;
    int p  = blockIdx.y;
    int rt = 0;
    while ((rt + 1) * (rt + 2) / 2 <= p) rt++;
    int ct = p - rt * (rt + 1) / 2;
    int j0 = jb * BK;
    int r0 = j0 + 64 + rt * 64, c0 = j0 + 64 + ct * 64;
    float* A = g_A + (size_t)k * NDIM * NDIM;
    const float* Li = &g_Linv[((size_t)k * NB + jb) * BK * BK];
    int tr = (threadIdx.x >> 4) * 4, tc = (threadIdx.x & 15) * 4;

    for (int t = threadIdx.x; t < 64 * 64; t += 256) {
        B2[t >> 6][t & 63] = Li[t];
        B1[t >> 6][t & 63] = A[(size_t)(r0 + (t >> 6)) * NDIM + j0 + (t & 63)];
    }
    __syncthreads();
    float accR[4][4] = {};
    for (int t = 0; t < 64; t++) {
        float a[4], b[4];
#pragma unroll
        for (int u = 0; u < 4; u++) { a[u] = B1[tr + u][t]; b[u] = B2[tc + u][t]; }
#pragma unroll
        for (int u = 0; u < 4; u++)
#pragma unroll
            for (int v = 0; v < 4; v++) accR[u][v] += a[u] * b[v];
    }
    float accC[4][4];
    if (ct != rt) {
        __syncthreads();
        for (int t = threadIdx.x; t < 64 * 64; t += 256)
            B1[t >> 6][t & 63] = A[(size_t)(c0 + (t >> 6)) * NDIM + j0 + (t & 63)];
        __syncthreads();
#pragma unroll
        for (int u = 0; u < 4; u++)
#pragma unroll
            for (int v = 0; v < 4; v++) accC[u][v] = 0.f;
        for (int t = 0; t < 64; t++) {
            float a[4], b[4];
#pragma unroll
            for (int u = 0; u < 4; u++) { a[u] = B1[tr + u][t]; b[u] = B2[tc + u][t]; }
#pragma unroll
            for (int u = 0; u < 4; u++)
#pragma unroll
                for (int v = 0; v < 4; v++) accC[u][v] += a[u] * b[v];
        }
    } else {
#pragma unroll
        for (int u = 0; u < 4; u++)
#pragma unroll
            for (int v = 0; v < 4; v++) accC[u][v] = accR[u][v];
    }
    __syncthreads();
#pragma unroll
    for (int u = 0; u < 4; u++)
#pragma unroll
        for (int v = 0; v < 4; v++) {
            B1[tr + u][tc + v] = accR[u][v];
            B2[tr + u][tc + v] = accC[u][v];
        }
    if (rt == ct) {
        float* Lm = g_Lm + (size_t)k * NDIM * NDIM;
#pragma unroll
        for (int u = 0; u < 4; u++)
#pragma unroll
            for (int v = 0; v < 4; v++)
                Lm[(size_t)(r0 + tr + u) * NDIM + j0 + tc + v] = accR[u][v];
    }
    __syncthreads();
    float acc3[4][4] = {};
    for (int t = 0; t < 64; t++) {
        float a[4], b[4];
#pragma unroll
        for (int u = 0; u < 4; u++) { a[u] = B1[tr + u][t]; b[u] = B2[tc + u][t]; }
#pragma unroll
        for (int u = 0; u < 4; u++)
#pragma unroll
            for (int v = 0; v < 4; v++) acc3[u][v] += a[u] * b[v];
    }
#pragma unroll
    for (int u = 0; u < 4; u++)
#pragma unroll
        for (int v = 0; v < 4; v++) {
            size_t idx = (size_t)(r0 + tr + u) * NDIM + c0 + tc + v;
            A[idx] -= acc3[u][v];
        }
}

// ---------------- W diag blocks ----------------
__global__ __launch_bounds__(256) void k_wdiag() {
    int k = blockIdx.x, j = blockIdx.y;
    const float* Li = &g_Linv[((size_t)k * NB + j) * BK * BK];
    float* W = g_Wm + (size_t)k * NDIM * NDIM;
    for (int t = threadIdx.x; t < 64 * 64; t += 256)
        W[(size_t)(j * 64 + (t >> 6)) * NDIM + j * 64 + (t & 63)] = Li[t];
}

// ---------------- W off-diag level d ----------------
__global__ __launch_bounds__(256) void k_winv(int d) {
    __shared__ float Ta[64][65];
    __shared__ float Tb[64][65];
    int k = blockIdx.x, j = blockIdx.y, i = j + d;
    const float* Lm = g_Lm + (size_t)k * NDIM * NDIM;
    float* W = g_Wm + (size_t)k * NDIM * NDIM;
    const float* Li = &g_Linv[((size_t)k * NB + i) * BK * BK];
    int tr = (threadIdx.x >> 4) * 4, tc = (threadIdx.x & 15) * 4;
    float acc[4][4] = {};
    for (int t = j; t < i; t++) {
        __syncthreads();
        for (int q = threadIdx.x; q < 64 * 64; q += 256) {
            Ta[q >> 6][q & 63] = Lm[(size_t)(i * 64 + (q >> 6)) * NDIM + t * 64 + (q & 63)];
            Tb[q >> 6][q & 63] = W[(size_t)(t * 64 + (q >> 6)) * NDIM + j * 64 + (q & 63)];
        }
        __syncthreads();
        for (int kk = 0; kk < 64; kk++) {
            float a[4], b[4];
#pragma unroll
            for (int u = 0; u < 4; u++) { a[u] = Ta[tr + u][kk]; b[u] = Tb[kk][tc + u]; }
#pragma unroll
            for (int u = 0; u < 4; u++)
#pragma unroll
                for (int v = 0; v < 4; v++) acc[u][v] += a[u] * b[v];
        }
    }
    __syncthreads();
#pragma unroll
    for (int u = 0; u < 4; u++)
#pragma unroll
        for (int v = 0; v < 4; v++) Ta[tr + u][tc + v] = acc[u][v];
    for (int q = threadIdx.x; q < 64 * 64; q += 256)
        Tb[q >> 6][q & 63] = Li[q];
    __syncthreads();
    float z[4][4] = {};
    for (int kk = 0; kk < 64; kk++) {
        float a[4], b[4];
#pragma unroll
        for (int u = 0; u < 4; u++) { a[u] = Tb[tr + u][kk]; b[u] = Ta[kk][tc + u]; }
#pragma unroll
        for (int u = 0; u < 4; u++)
#pragma unroll
            for (int v = 0; v < 4; v++) z[u][v] += a[u] * b[v];
    }
#pragma unroll
    for (int u = 0; u < 4; u++)
#pragma unroll
        for (int v = 0; v < 4; v++)
            W[(size_t)(i * 64 + tr + u) * NDIM + j * 64 + tc + v] = -z[u][v];
}

// ---------------- s via tf32 tensor cores ----------------
// C(128x128) = W[m0:m0+128, :] @ F^T[:, n0:n0+128]; s += colsum(C^2). Z never hits DRAM.
// grid (N/128, NDIM/128, NOUT), block 256 (8 warps as 4x2 over (M,N)); warp tile 32x64.
__global__ __launch_bounds__(256) void k_s() {
    __shared__ float Ws[128][33];
    __shared__ float Fs[128][33];
    __shared__ float red[4][128];
    int n0 = blockIdx.x * 128;
    int i2 = blockIdx.y;
    int m0 = i2 * 128;
    int k  = blockIdx.z;
    const float* Wk = g_Wm + (size_t)k * NDIM * NDIM;

    int tid  = threadIdx.x;
    int wid  = tid >> 5, lane = tid & 31;
    int wm   = wid >> 1, wn = wid & 1;       // warp grid 4x2
    int mbase = wm * 32, nbase = wn * 64;
    int g    = lane >> 2, tq = lane & 3;     // mma group / thread-in-group

    // gmem->smem mapping: thread loads one row-half (16 floats) per array
    int lrow = tid >> 1, lhalf = (tid & 1) * 16;

    float c[2][8][4];
#pragma unroll
    for (int mt = 0; mt < 2; mt++)
#pragma unroll
        for (int nt = 0; nt < 8; nt++)
#pragma unroll
            for (int q = 0; q < 4; q++) c[mt][nt][q] = 0.f;

    int Kend = m0 + 128;                     // W lower-triangular: cols > m are zero
    for (int k0 = 0; k0 < Kend; k0 += 32) {
        const float* wp = &Wk[(size_t)(m0 + lrow) * NDIM + k0 + lhalf];
        const float* fp = &g_F[(size_t)(n0 + lrow) * NDIM + k0 + lhalf];
        float4 w0 = *(const float4*)&wp[0],  w1 = *(const float4*)&wp[4];
        float4 w2 = *(const float4*)&wp[8],  w3 = *(const float4*)&wp[12];
        float4 f0 = *(const float4*)&fp[0],  f1 = *(const float4*)&fp[4];
        float4 f2 = *(const float4*)&fp[8],  f3 = *(const float4*)&fp[12];
        __syncthreads();
        float* wd = &Ws[lrow][lhalf];
        float* fd = &Fs[lrow][lhalf];
        wd[0]  = __uint_as_float(f2tf32(w0.x)); wd[1]  = __uint_as_float(f2tf32(w0.y));
        wd[2]  = __uint_as_float(f2tf32(w0.z)); wd[3]  = __uint_as_float(f2tf32(w0.w));
        wd[4]  = __uint_as_float(f2tf32(w1.x)); wd[5]  = __uint_as_float(f2tf32(w1.y));
        wd[6]  = __uint_as_float(f2tf32(w1.z)); wd[7]  = __uint_as_float(f2tf32(w1.w));
        wd[8]  = __uint_as_float(f2tf32(w2.x)); wd[9]  = __uint_as_float(f2tf32(w2.y));
        wd[10] = __uint_as_float(f2tf32(w2.z)); wd[11] = __uint_as_float(f2tf32(w2.w));
        wd[12] = __uint_as_float(f2tf32(w3.x)); wd[13] = __uint_as_float(f2tf32(w3.y));
        wd[14] = __uint_as_float(f2tf32(w3.z)); wd[15] = __uint_as_float(f2tf32(w3.w));
        fd[0]  = __uint_as_float(f2tf32(f0.x)); fd[1]  = __uint_as_float(f2tf32(f0.y));
        fd[2]  = __uint_as_float(f2tf32(f0.z)); fd[3]  = __uint_as_float(f2tf32(f0.w));
        fd[4]  = __uint_as_float(f2tf32(f1.x)); fd[5]  = __uint_as_float(f2tf32(f1.y));
        fd[6]  = __uint_as_float(f2tf32(f1.z)); fd[7]  = __uint_as_float(f2tf32(f1.w));
        fd[8]  = __uint_as_float(f2tf32(f2.x)); fd[9]  = __uint_as_float(f2tf32(f2.y));
        fd[10] = __uint_as_float(f2tf32(f2.z)); fd[11] = __uint_as_float(f2tf32(f2.w));
        fd[12] = __uint_as_float(f2tf32(f3.x)); fd[13] = __uint_as_float(f2tf32(f3.y));
        fd[14] = __uint_as_float(f2tf32(f3.z)); fd[15] = __uint_as_float(f2tf32(f3.w));
        __syncthreads();

#pragma unroll
        for (int kk = 0; kk < 32; kk += 8) {
            unsigned b0[8], b1[8];
#pragma unroll
            for (int nt = 0; nt < 8; nt++) {
                b0[nt] = __float_as_uint(Fs[nbase + nt * 8 + g][kk + tq]);
                b1[nt] = __float_as_uint(Fs[nbase + nt * 8 + g][kk + tq + 4]);
            }
#pragma unroll
            for (int mt = 0; mt < 2; mt++) {
                unsigned a0 = __float_as_uint(Ws[mbase + mt * 16 + g][kk + tq]);
                unsigned a1 = __float_as_uint(Ws[mbase + mt * 16 + g + 8][kk + tq]);
                unsigned a2 = __float_as_uint(Ws[mbase + mt * 16 + g][kk + tq + 4]);
                unsigned a3 = __float_as_uint(Ws[mbase + mt * 16 + g + 8][kk + tq + 4]);
#pragma unroll
                for (int nt = 0; nt < 8; nt++) {
                    asm volatile(
                        "mma.sync.aligned.m16n8k8.row.col.f32.tf32.tf32.f32 "
                        "{%0,%1,%2,%3}, {%4,%5,%6,%7}, {%8,%9}, {%0,%1,%2,%3};"
                        : "+f"(c[mt][nt][0]), "+f"(c[mt][nt][1]),
                          "+f"(c[mt][nt][2]), "+f"(c[mt][nt][3])
                        : "r"(a0), "r"(a1), "r"(a2), "r"(a3),
                          "r"(b0[nt]), "r"(b1[nt]));
                }
            }
        }
    }

    // epilogue: s_col = sum over rows of z^2
#pragma unroll
    for (int nt = 0; nt < 8; nt++) {
        float s0 = c[0][nt][0] * c[0][nt][0] + c[0][nt][2] * c[0][nt][2]
                 + c[1][nt][0] * c[1][nt][0] + c[1][nt][2] * c[1][nt][2];
        float s1 = c[0][nt][1] * c[0][nt][1] + c[0][nt][3] * c[0][nt][3]
                 + c[1][nt][1] * c[1][nt][1] + c[1][nt][3] * c[1][nt][3];
        s0 += __shfl_down_sync(0xffffffffu, s0, 16);
        s0 += __shfl_down_sync(0xffffffffu, s0, 8);
        s0 += __shfl_down_sync(0xffffffffu, s0, 4);
        s1 += __shfl_down_sync(0xffffffffu, s1, 16);
        s1 += __shfl_down_sync(0xffffffffu, s1, 8);
        s1 += __shfl_down_sync(0xffffffffu, s1, 4);
        if (lane < 4) {
            red[wm][nbase + nt * 8 + lane * 2]     = s0;
            red[wm][nbase + nt * 8 + lane * 2 + 1] = s1;
        }
    }
    __syncthreads();
    if (tid < 128) {
        float tot = red[0][tid] + red[1][tid] + red[2][tid] + red[3][tid];
        g_spart[((size_t)k * (NDIM / TS) + i2) * N + n0 + tid] = tot;
    }
}

// ---------------- reduce s partials ----------------
__global__ __launch_bounds__(256) void k_sred(float* __restrict__ out_s) {
    int idx = blockIdx.x * 256 + threadIdx.x;
    int n = idx >> 4, k = idx & 15;
    float tot = 0.f;
#pragma unroll
    for (int i2 = 0; i2 < NDIM / TS; i2++)
        tot += g_spart[((size_t)k * (NDIM / TS) + i2) * N + n];
    out_s[idx] = tot;
}

// ---------------- launch ----------------
extern "C" void kernel_launch(void* const* d_in, const int* in_sizes, int n_in,
                              void* d_out, int out_size) {
    const float* x  = (const float*)d_in[0];
    const float* Wf = (const float*)d_in[1];
    const float* w  = (const float*)d_in[2];
    const float* P  = (const float*)d_in[3];
    float* out   = (float*)d_out;
    float* out_m = out;
    float* out_s = out + (size_t)N * NOUT;

    k_F<<<dim3(NDIM / 256, N / 16), 256>>>(x, Wf);
    k_m<<<N / 8, 256>>>(w, out_m);
    k_prep<<<(unsigned)((size_t)NOUT * NDIM * NDIM / (256 * 4)), 256>>>(P);

    for (int jb = 0; jb < NB; jb++) {
        k_diag<<<NOUT, 64>>>(jb);
        int nt = NB - 1 - jb;
        if (nt > 0)
            k_step<<<dim3(NOUT, nt * (nt + 1) / 2), 256>>>(jb);
    }
    k_wdiag<<<dim3(NOUT, NB), 256>>>();
    for (int d = 1; d < NB; d++)
        k_winv<<<dim3(NOUT, NB - d), 256>>>(d);

    k_s<<<dim3(N / 128, NDIM / 128, NOUT), 256>>>();
    k_sred<<<(N * NOUT) / 256, 256>>>(out_s);
}

// round 7
// speedup vs baseline: 1.4076x; 1.0942x over previous
#include <cuda_runtime.h>
#include <math.h>

#define N      4096
#define NDIM   1024
#define NOUT   16
#define DIN    64
#define BK     64
#define NB     (NDIM/BK)   // 16
#define TS     128         // s-kernel tile

// ---------------- scratch (device globals) ----------------
__device__ float g_F[(size_t)N * NDIM];                 // F = tanh(x Wf), [n][i]
__device__ float g_A[(size_t)NOUT * NDIM * NDIM];       // working trailing matrix
__device__ float g_Lm[(size_t)NOUT * NDIM * NDIM];      // L off-diag panel tiles
__device__ float g_Wm[(size_t)NOUT * NDIM * NDIM];      // W = L^{-1} (dense, upper zeroed)
__device__ float g_Linv[(size_t)NOUT * NB * BK * BK];   // diag-block inverses
__device__ float g_spart[(size_t)NOUT * (NDIM / TS) * N]; // s partials [k][i2][n]

__device__ __forceinline__ unsigned f2tf32(float x) {
    unsigned r;
    asm("cvt.rna.tf32.f32 %0, %1;" : "=r"(r) : "f"(x));
    return r;
}

// ---------------- F = tanh(x @ Wf) ----------------
__global__ __launch_bounds__(256) void k_F(const float* __restrict__ x,
                                           const float* __restrict__ Wf) {
    __shared__ float xs[16][DIN];
    int n0 = blockIdx.y * 16;
    int i  = blockIdx.x * 256 + threadIdx.x;
    for (int t = threadIdx.x; t < 16 * DIN; t += 256)
        xs[t >> 6][t & 63] = x[(size_t)(n0 + (t >> 6)) * DIN + (t & 63)];
    __syncthreads();
    float acc[16];
#pragma unroll
    for (int nn = 0; nn < 16; nn++) acc[nn] = 0.f;
    for (int d = 0; d < DIN; d++) {
        float wf = Wf[(size_t)d * NDIM + i];
#pragma unroll
        for (int nn = 0; nn < 16; nn++) acc[nn] += xs[nn][d] * wf;
    }
#pragma unroll
    for (int nn = 0; nn < 16; nn++)
        g_F[(size_t)(n0 + nn) * NDIM + i] = tanhf(acc[nn]);
}

// ---------------- m = F @ w^T ----------------
__global__ __launch_bounds__(256) void k_m(const float* __restrict__ w,
                                           float* __restrict__ out_m) {
    int warp = threadIdx.x >> 5, lane = threadIdx.x & 31;
    int n = blockIdx.x * 8 + warp;
    const float* Frow = &g_F[(size_t)n * NDIM];
    for (int k = 0; k < NOUT; k++) {
        float s = 0.f;
        for (int i = lane; i < NDIM; i += 32) s += Frow[i] * w[(size_t)k * NDIM + i];
#pragma unroll
        for (int o = 16; o > 0; o >>= 1) s += __shfl_down_sync(0xffffffffu, s, o);
        if (lane == 0) out_m[(size_t)n * NOUT + k] = s;
    }
}

// ---------------- copy P -> A (float4) and zero W ----------------
__global__ __launch_bounds__(256) void k_prep(const float* __restrict__ P) {
    size_t idx = ((size_t)blockIdx.x * 256 + threadIdx.x) * 4;
    *(float4*)&g_A[idx]  = *(const float4*)&P[idx];
    float4 z = {0.f, 0.f, 0.f, 0.f};
    *(float4*)&g_Wm[idx] = z;
}

// ---------------- diag block: fast LDL-style factor + warp-parallel inverse ----------------
// grid NOUT, block 256. Thread owns elements (r = (tid>>6)+4i, c = tid&63), i<16.
__global__ __launch_bounds__(256) void k_diag(int jb) {
    __shared__ float D[64][65];
    __shared__ float X[64][65];
    __shared__ float invrt[64];
    int k   = blockIdx.x;
    int tid = threadIdx.x;
    int j0  = jb * BK;
    int br  = tid >> 6, c = tid & 63;
    float* A = g_A + (size_t)k * NDIM * NDIM;

#pragma unroll
    for (int i = 0; i < 16; i++) {
        int r = br + i * 4;
        D[r][c] = A[(size_t)(j0 + r) * NDIM + j0 + c];
    }
    __syncthreads();

    // LDL-style elimination (division-free column scaling, one bar per step)
    for (int j = 0; j < 64; j++) {
        float i2  = __frcp_rn(D[j][j]);
        float dcj = (c > j) ? D[c][j] * i2 : 0.f;   // l_cj
#pragma unroll
        for (int i = 0; i < 16; i++) {
            int r = br + i * 4;
            if (r > j && c > j && c <= r)
                D[r][c] -= D[r][j] * dcj;
        }
        __syncthreads();
    }

    // convert to Cholesky L in-place; init X = I*invrt (upper zero)
    if (tid < 64) invrt[tid] = rsqrtf(D[tid][tid]);
    __syncthreads();
    float rc = invrt[c];
#pragma unroll
    for (int i = 0; i < 16; i++) {
        int r = br + i * 4;
        if (c <= r) D[r][c] *= rc;          // L[r][c]
        X[r][c] = (r == c) ? invrt[c] : 0.f;
    }
    __syncthreads();

    // invert L: warp w handles columns {w, w+8, ..., w+56}, 4 lanes per column
    {
        int w    = tid >> 5, lane = tid & 31;
        int ci   = w + ((lane >> 2) << 3);
        int sub  = lane & 3;
        for (int r = 1; r < 64; r++) {
            float s = 0.f;
            for (int t = ci + sub; t < r; t += 4) s += D[r][t] * X[t][ci];
            s += __shfl_xor_sync(0xffffffffu, s, 1);
            s += __shfl_xor_sync(0xffffffffu, s, 2);
            if (sub == 0 && r > ci) X[r][ci] = -s * invrt[r];
            __syncwarp();
        }
    }
    __syncthreads();

    float* Lout = &g_Linv[((size_t)k * NB + jb) * BK * BK];
#pragma unroll
    for (int i = 0; i < 16; i++) {
        int r = br + i * 4;
        Lout[r * 64 + c] = X[r][c];
    }
}

// ---------------- fused panel TRSM (from Linv) + SYRK ----------------
__global__ __launch_bounds__(256) void k_step(int jb) {
    __shared__ float B1[64][65];
    __shared__ float B2[64][65];
    int k  = blockIdx.x;
    int p  = blockIdx.y;
    int rt = 0;
    while ((rt + 1) * (rt + 2) / 2 <= p) rt++;
    int ct = p - rt * (rt + 1) / 2;
    int j0 = jb * BK;
    int r0 = j0 + 64 + rt * 64, c0 = j0 + 64 + ct * 64;
    float* A = g_A + (size_t)k * NDIM * NDIM;
    const float* Li = &g_Linv[((size_t)k * NB + jb) * BK * BK];
    int tr = (threadIdx.x >> 4) * 4, tc = (threadIdx.x & 15) * 4;

    for (int t = threadIdx.x; t < 64 * 64; t += 256) {
        B2[t >> 6][t & 63] = Li[t];
        B1[t >> 6][t & 63] = A[(size_t)(r0 + (t >> 6)) * NDIM + j0 + (t & 63)];
    }
    __syncthreads();
    float accR[4][4] = {};
    for (int t = 0; t < 64; t++) {
        float a[4], b[4];
#pragma unroll
        for (int u = 0; u < 4; u++) { a[u] = B1[tr + u][t]; b[u] = B2[tc + u][t]; }
#pragma unroll
        for (int u = 0; u < 4; u++)
#pragma unroll
            for (int v = 0; v < 4; v++) accR[u][v] += a[u] * b[v];
    }
    float accC[4][4];
    if (ct != rt) {
        __syncthreads();
        for (int t = threadIdx.x; t < 64 * 64; t += 256)
            B1[t >> 6][t & 63] = A[(size_t)(c0 + (t >> 6)) * NDIM + j0 + (t & 63)];
        __syncthreads();
#pragma unroll
        for (int u = 0; u < 4; u++)
#pragma unroll
            for (int v = 0; v < 4; v++) accC[u][v] = 0.f;
        for (int t = 0; t < 64; t++) {
            float a[4], b[4];
#pragma unroll
            for (int u = 0; u < 4; u++) { a[u] = B1[tr + u][t]; b[u] = B2[tc + u][t]; }
#pragma unroll
            for (int u = 0; u < 4; u++)
#pragma unroll
                for (int v = 0; v < 4; v++) accC[u][v] += a[u] * b[v];
        }
    } else {
#pragma unroll
        for (int u = 0; u < 4; u++)
#pragma unroll
            for (int v = 0; v < 4; v++) accC[u][v] = accR[u][v];
    }
    __syncthreads();
#pragma unroll
    for (int u = 0; u < 4; u++)
#pragma unroll
        for (int v = 0; v < 4; v++) {
            B1[tr + u][tc + v] = accR[u][v];
            B2[tr + u][tc + v] = accC[u][v];
        }
    if (rt == ct) {
        float* Lm = g_Lm + (size_t)k * NDIM * NDIM;
#pragma unroll
        for (int u = 0; u < 4; u++)
#pragma unroll
            for (int v = 0; v < 4; v++)
                Lm[(size_t)(r0 + tr + u) * NDIM + j0 + tc + v] = accR[u][v];
    }
    __syncthreads();
    float acc3[4][4] = {};
    for (int t = 0; t < 64; t++) {
        float a[4], b[4];
#pragma unroll
        for (int u = 0; u < 4; u++) { a[u] = B1[tr + u][t]; b[u] = B2[tc + u][t]; }
#pragma unroll
        for (int u = 0; u < 4; u++)
#pragma unroll
            for (int v = 0; v < 4; v++) acc3[u][v] += a[u] * b[v];
    }
#pragma unroll
    for (int u = 0; u < 4; u++)
#pragma unroll
        for (int v = 0; v < 4; v++) {
            size_t idx = (size_t)(r0 + tr + u) * NDIM + c0 + tc + v;
            A[idx] -= acc3[u][v];
        }
}

// ---------------- W diag blocks ----------------
__global__ __launch_bounds__(256) void k_wdiag() {
    int k = blockIdx.x, j = blockIdx.y;
    const float* Li = &g_Linv[((size_t)k * NB + j) * BK * BK];
    float* W = g_Wm + (size_t)k * NDIM * NDIM;
    for (int t = threadIdx.x; t < 64 * 64; t += 256)
        W[(size_t)(j * 64 + (t >> 6)) * NDIM + j * 64 + (t & 63)] = Li[t];
}

// ---------------- W off-diag level d ----------------
__global__ __launch_bounds__(256) void k_winv(int d) {
    __shared__ float Ta[64][65];
    __shared__ float Tb[64][65];
    int k = blockIdx.x, j = blockIdx.y, i = j + d;
    const float* Lm = g_Lm + (size_t)k * NDIM * NDIM;
    float* W = g_Wm + (size_t)k * NDIM * NDIM;
    const float* Li = &g_Linv[((size_t)k * NB + i) * BK * BK];
    int tr = (threadIdx.x >> 4) * 4, tc = (threadIdx.x & 15) * 4;
    float acc[4][4] = {};
    for (int t = j; t < i; t++) {
        __syncthreads();
        for (int q = threadIdx.x; q < 64 * 64; q += 256) {
            Ta[q >> 6][q & 63] = Lm[(size_t)(i * 64 + (q >> 6)) * NDIM + t * 64 + (q & 63)];
            Tb[q >> 6][q & 63] = W[(size_t)(t * 64 + (q >> 6)) * NDIM + j * 64 + (q & 63)];
        }
        __syncthreads();
        for (int kk = 0; kk < 64; kk++) {
            float a[4], b[4];
#pragma unroll
            for (int u = 0; u < 4; u++) { a[u] = Ta[tr + u][kk]; b[u] = Tb[kk][tc + u]; }
#pragma unroll
            for (int u = 0; u < 4; u++)
#pragma unroll
                for (int v = 0; v < 4; v++) acc[u][v] += a[u] * b[v];
        }
    }
    __syncthreads();
#pragma unroll
    for (int u = 0; u < 4; u++)
#pragma unroll
        for (int v = 0; v < 4; v++) Ta[tr + u][tc + v] = acc[u][v];
    for (int q = threadIdx.x; q < 64 * 64; q += 256)
        Tb[q >> 6][q & 63] = Li[q];
    __syncthreads();
    float z[4][4] = {};
    for (int kk = 0; kk < 64; kk++) {
        float a[4], b[4];
#pragma unroll
        for (int u = 0; u < 4; u++) { a[u] = Tb[tr + u][kk]; b[u] = Ta[kk][tc + u]; }
#pragma unroll
        for (int u = 0; u < 4; u++)
#pragma unroll
            for (int v = 0; v < 4; v++) z[u][v] += a[u] * b[v];
    }
#pragma unroll
    for (int u = 0; u < 4; u++)
#pragma unroll
        for (int v = 0; v < 4; v++)
            W[(size_t)(i * 64 + tr + u) * NDIM + j * 64 + tc + v] = -z[u][v];
}

// ---------------- s via tf32 tensor cores ----------------
// C(128x128) = W[m0:m0+128, :] @ F^T[:, n0:n0+128]; s += colsum(C^2). Z never hits DRAM.
// grid (N/128, NDIM/128, NOUT), block 256 (8 warps as 4x2 over (M,N)); warp tile 32x64.
__global__ __launch_bounds__(256) void k_s() {
    __shared__ float Ws[128][33];
    __shared__ float Fs[128][33];
    __shared__ float red[4][128];
    int n0 = blockIdx.x * 128;
    int i2 = blockIdx.y;
    int m0 = i2 * 128;
    int k  = blockIdx.z;
    const float* Wk = g_Wm + (size_t)k * NDIM * NDIM;

    int tid  = threadIdx.x;
    int wid  = tid >> 5, lane = tid & 31;
    int wm   = wid >> 1, wn = wid & 1;       // warp grid 4x2
    int mbase = wm * 32, nbase = wn * 64;
    int g    = lane >> 2, tq = lane & 3;     // mma group / thread-in-group

    // gmem->smem mapping: thread loads one row-half (16 floats) per array
    int lrow = tid >> 1, lhalf = (tid & 1) * 16;

    float c[2][8][4];
#pragma unroll
    for (int mt = 0; mt < 2; mt++)
#pragma unroll
        for (int nt = 0; nt < 8; nt++)
#pragma unroll
            for (int q = 0; q < 4; q++) c[mt][nt][q] = 0.f;

    int Kend = m0 + 128;                     // W lower-triangular: cols > m are zero
    for (int k0 = 0; k0 < Kend; k0 += 32) {
        const float* wp = &Wk[(size_t)(m0 + lrow) * NDIM + k0 + lhalf];
        const float* fp = &g_F[(size_t)(n0 + lrow) * NDIM + k0 + lhalf];
        float4 w0 = *(const float4*)&wp[0],  w1 = *(const float4*)&wp[4];
        float4 w2 = *(const float4*)&wp[8],  w3 = *(const float4*)&wp[12];
        float4 f0 = *(const float4*)&fp[0],  f1 = *(const float4*)&fp[4];
        float4 f2 = *(const float4*)&fp[8],  f3 = *(const float4*)&fp[12];
        __syncthreads();
        float* wd = &Ws[lrow][lhalf];
        float* fd = &Fs[lrow][lhalf];
        wd[0]  = __uint_as_float(f2tf32(w0.x)); wd[1]  = __uint_as_float(f2tf32(w0.y));
        wd[2]  = __uint_as_float(f2tf32(w0.z)); wd[3]  = __uint_as_float(f2tf32(w0.w));
        wd[4]  = __uint_as_float(f2tf32(w1.x)); wd[5]  = __uint_as_float(f2tf32(w1.y));
        wd[6]  = __uint_as_float(f2tf32(w1.z)); wd[7]  = __uint_as_float(f2tf32(w1.w));
        wd[8]  = __uint_as_float(f2tf32(w2.x)); wd[9]  = __uint_as_float(f2tf32(w2.y));
        wd[10] = __uint_as_float(f2tf32(w2.z)); wd[11] = __uint_as_float(f2tf32(w2.w));
        wd[12] = __uint_as_float(f2tf32(w3.x)); wd[13] = __uint_as_float(f2tf32(w3.y));
        wd[14] = __uint_as_float(f2tf32(w3.z)); wd[15] = __uint_as_float(f2tf32(w3.w));
        fd[0]  = __uint_as_float(f2tf32(f0.x)); fd[1]  = __uint_as_float(f2tf32(f0.y));
        fd[2]  = __uint_as_float(f2tf32(f0.z)); fd[3]  = __uint_as_float(f2tf32(f0.w));
        fd[4]  = __uint_as_float(f2tf32(f1.x)); fd[5]  = __uint_as_float(f2tf32(f1.y));
        fd[6]  = __uint_as_float(f2tf32(f1.z)); fd[7]  = __uint_as_float(f2tf32(f1.w));
        fd[8]  = __uint_as_float(f2tf32(f2.x)); fd[9]  = __uint_as_float(f2tf32(f2.y));
        fd[10] = __uint_as_float(f2tf32(f2.z)); fd[11] = __uint_as_float(f2tf32(f2.w));
        fd[12] = __uint_as_float(f2tf32(f3.x)); fd[13] = __uint_as_float(f2tf32(f3.y));
        fd[14] = __uint_as_float(f2tf32(f3.z)); fd[15] = __uint_as_float(f2tf32(f3.w));
        __syncthreads();

#pragma unroll
        for (int kk = 0; kk < 32; kk += 8) {
            unsigned b0[8], b1[8];
#pragma unroll
            for (int nt = 0; nt < 8; nt++) {
                b0[nt] = __float_as_uint(Fs[nbase + nt * 8 + g][kk + tq]);
                b1[nt] = __float_as_uint(Fs[nbase + nt * 8 + g][kk + tq + 4]);
            }
#pragma unroll
            for (int mt = 0; mt < 2; mt++) {
                unsigned a0 = __float_as_uint(Ws[mbase + mt * 16 + g][kk + tq]);
                unsigned a1 = __float_as_uint(Ws[mbase + mt * 16 + g + 8][kk + tq]);
                unsigned a2 = __float_as_uint(Ws[mbase + mt * 16 + g][kk + tq + 4]);
                unsigned a3 = __float_as_uint(Ws[mbase + mt * 16 + g + 8][kk + tq + 4]);
#pragma unroll
                for (int nt = 0; nt < 8; nt++) {
                    asm volatile(
                        "mma.sync.aligned.m16n8k8.row.col.f32.tf32.tf32.f32 "
                        "{%0,%1,%2,%3}, {%4,%5,%6,%7}, {%8,%9}, {%0,%1,%2,%3};"
                        : "+f"(c[mt][nt][0]), "+f"(c[mt][nt][1]),
                          "+f"(c[mt][nt][2]), "+f"(c[mt][nt][3])
                        : "r"(a0), "r"(a1), "r"(a2), "r"(a3),
                          "r"(b0[nt]), "r"(b1[nt]));
                }
            }
        }
    }

    // epilogue: s_col = sum over rows of z^2
#pragma unroll
    for (int nt = 0; nt < 8; nt++) {
        float s0 = c[0][nt][0] * c[0][nt][0] + c[0][nt][2] * c[0][nt][2]
                 + c[1][nt][0] * c[1][nt][0] + c[1][nt][2] * c[1][nt][2];
        float s1 = c[0][nt][1] * c[0][nt][1] + c[0][nt][3] * c[0][nt][3]
                 + c[1][nt][1] * c[1][nt][1] + c[1][nt][3] * c[1][nt][3];
        s0 += __shfl_down_sync(0xffffffffu, s0, 16);
        s0 += __shfl_down_sync(0xffffffffu, s0, 8);
        s0 += __shfl_down_sync(0xffffffffu, s0, 4);
        s1 += __shfl_down_sync(0xffffffffu, s1, 16);
        s1 += __shfl_down_sync(0xffffffffu, s1, 8);
        s1 += __shfl_down_sync(0xffffffffu, s1, 4);
        if (lane < 4) {
            red[wm][nbase + nt * 8 + lane * 2]     = s0;
            red[wm][nbase + nt * 8 + lane * 2 + 1] = s1;
        }
    }
    __syncthreads();
    if (tid < 128) {
        float tot = red[0][tid] + red[1][tid] + red[2][tid] + red[3][tid];
        g_spart[((size_t)k * (NDIM / TS) + i2) * N + n0 + tid] = tot;
    }
}

// ---------------- reduce s partials ----------------
__global__ __launch_bounds__(256) void k_sred(float* __restrict__ out_s) {
    int idx = blockIdx.x * 256 + threadIdx.x;
    int n = idx >> 4, k = idx & 15;
    float tot = 0.f;
#pragma unroll
    for (int i2 = 0; i2 < NDIM / TS; i2++)
        tot += g_spart[((size_t)k * (NDIM / TS) + i2) * N + n];
    out_s[idx] = tot;
}

// ---------------- launch ----------------
extern "C" void kernel_launch(void* const* d_in, const int* in_sizes, int n_in,
                              void* d_out, int out_size) {
    const float* x  = (const float*)d_in[0];
    const float* Wf = (const float*)d_in[1];
    const float* w  = (const float*)d_in[2];
    const float* P  = (const float*)d_in[3];
    float* out   = (float*)d_out;
    float* out_m = out;
    float* out_s = out + (size_t)N * NOUT;

    k_F<<<dim3(NDIM / 256, N / 16), 256>>>(x, Wf);
    k_m<<<N / 8, 256>>>(w, out_m);
    k_prep<<<(unsigned)((size_t)NOUT * NDIM * NDIM / (256 * 4)), 256>>>(P);

    for (int jb = 0; jb < NB; jb++) {
        k_diag<<<NOUT, 256>>>(jb);
        int nt = NB - 1 - jb;
        if (nt > 0)
            k_step<<<dim3(NOUT, nt * (nt + 1) / 2), 256>>>(jb);
    }
    k_wdiag<<<dim3(NOUT, NB), 256>>>();
    for (int d = 1; d < NB; d++)
        k_winv<<<dim3(NOUT, NB - d), 256>>>(d);

    k_s<<<dim3(N / 128, NDIM / 128, NOUT), 256>>>();
    k_sred<<<(N * NOUT) / 256, 256>>>(out_s);
}